// round 11
// baseline (speedup 1.0000x reference)
#include <cuda_runtime.h>
#include <cuda_fp16.h>
#include <cstdint>
#include <math.h>

#define D_DIM 1024
#define H_DIM 512
#define E_NUM 16
#define NTOK  4096
#define KSEL  8
#define NK    (NTOK * KSEL)

// ---------------------------------------------------------------------------
// Device scratch
// ---------------------------------------------------------------------------
__device__ float g_gwn[E_NUM * D_DIM];
__device__ int   g_idx[NK];
__device__ float g_w[NK];
__device__ int   g_cnt[E_NUM];
__device__ int   g_pos[E_NUM];
__device__ int   g_tok[NK + 256];
__device__ float g_tw[NK + 256];
__device__ int   g_pmap[NK];

__device__ __half g_xt[(size_t)NTOK * D_DIM];                // fp16 x
__device__ __half g_wguT[(size_t)E_NUM * 2 * H_DIM * D_DIM]; // [E][2H][D] interleaved gate/up
__device__ __half g_wdT [(size_t)E_NUM * D_DIM * H_DIM];     // [E][D][H]
__device__ __half g_swguT[(size_t)2 * H_DIM * D_DIM];
__device__ __half g_swdT [(size_t)D_DIM * H_DIM];

__device__ __half g_h [((size_t)NK + 256) * H_DIM];          // routed hidden (weighted)
__device__ __half g_hs[(size_t)NTOK * H_DIM];                // shared hidden
__device__ __half g_yh[(size_t)NK * D_DIM];                  // routed down output (fp16)

// ---------------------------------------------------------------------------
// Helpers (sm_80-compatible PTX only — harness compiles for plain sm_100)
// ---------------------------------------------------------------------------
__device__ __forceinline__ uint32_t smem_u32(const void* p) {
    uint32_t a;
    asm("{ .reg .u64 t; cvta.to.shared.u64 t, %1; cvt.u32.u64 %0, t; }" : "=r"(a) : "l"(p));
    return a;
}
__device__ __forceinline__ void cp16(uint32_t dst, const void* src) {
    asm volatile("cp.async.cg.shared.global [%0], [%1], 16;" :: "r"(dst), "l"(src));
}
#define CP_COMMIT() asm volatile("cp.async.commit_group;" ::: "memory")
#define CP_WAIT1()  asm volatile("cp.async.wait_group 1;" ::: "memory")
#define CP_WAIT0()  asm volatile("cp.async.wait_group 0;" ::: "memory")

__device__ __forceinline__ void ldm4(uint32_t& r0, uint32_t& r1, uint32_t& r2, uint32_t& r3,
                                     uint32_t a) {
    asm volatile("ldmatrix.sync.aligned.m8n8.x4.shared.b16 {%0,%1,%2,%3}, [%4];"
                 : "=r"(r0), "=r"(r1), "=r"(r2), "=r"(r3) : "r"(a));
}
__device__ __forceinline__ void mma16(float* c, const uint32_t* a, uint32_t b0, uint32_t b1) {
    asm volatile("mma.sync.aligned.m16n8k16.row.col.f32.f16.f16.f32 "
                 "{%0,%1,%2,%3}, {%4,%5,%6,%7}, {%8,%9}, {%0,%1,%2,%3};"
                 : "+f"(c[0]), "+f"(c[1]), "+f"(c[2]), "+f"(c[3])
                 : "r"(a[0]), "r"(a[1]), "r"(a[2]), "r"(a[3]), "r"(b0), "r"(b1));
}

// ---------------------------------------------------------------------------
// prep2: fused weight transposes (+fp16, +gate/up interleave) AND gwnorm.
// grid (32, 16, 52), block (32, 8).
// ---------------------------------------------------------------------------
__global__ void prep2_kernel(const float* __restrict__ gw,
                             const float* __restrict__ wg, const float* __restrict__ wu,
                             const float* __restrict__ wd, const float* __restrict__ swg,
                             const float* __restrict__ swu, const float* __restrict__ swd,
                             __half* __restrict__ wguT, __half* __restrict__ wdT,
                             __half* __restrict__ swguT, __half* __restrict__ swdT) {
    const int z = blockIdx.z;
    const int tx = threadIdx.x, ty = threadIdx.y;

    if (z == 51) {
        if (blockIdx.y != 0 || blockIdx.x >= E_NUM) return;
        const int e = blockIdx.x;
        const int t = ty * 32 + tx;
        if (e == 0 && t < E_NUM) { g_cnt[t] = 0; g_pos[t] = 0; }
        __shared__ float red[8];
        float ss = 0.f;
        for (int i = t; i < D_DIM; i += 256) { float v = gw[e * D_DIM + i]; ss += v * v; }
        for (int o = 16; o; o >>= 1) ss += __shfl_down_sync(0xFFFFFFFFu, ss, o);
        if ((t & 31) == 0) red[t >> 5] = ss;
        __syncthreads();
        __shared__ float s_inv;
        if (t == 0) {
            float tot = 0.f;
            for (int i = 0; i < 8; i++) tot += red[i];
            s_inv = 1.0f / fmaxf(sqrtf(tot), 1e-12f);
        }
        __syncthreads();
        float inv = s_inv;
        for (int i = t; i < D_DIM; i += 256) g_gwn[e * D_DIM + i] = gw[e * D_DIM + i] * inv;
        return;
    }

    const float* src; __half* dst;
    int R, C, mul, add;
    size_t bi, bo;
    if (z < 16)       { int e = z;      src = wg;  dst = wguT;  R = D_DIM; C = H_DIM; mul = 2; add = 0; bi = (size_t)e * R * C; bo = bi * 2; }
    else if (z < 32)  { int e = z - 16; src = wu;  dst = wguT;  R = D_DIM; C = H_DIM; mul = 2; add = 1; bi = (size_t)e * R * C; bo = bi * 2; }
    else if (z < 48)  { int e = z - 32; src = wd;  dst = wdT;   R = H_DIM; C = D_DIM; mul = 1; add = 0; bi = (size_t)e * R * C; bo = bi; }
    else if (z == 48) { src = swg; dst = swguT; R = D_DIM; C = H_DIM; mul = 2; add = 0; bi = 0; bo = 0; }
    else if (z == 49) { src = swu; dst = swguT; R = D_DIM; C = H_DIM; mul = 2; add = 1; bi = 0; bo = 0; }
    else              { src = swd; dst = swdT;  R = H_DIM; C = D_DIM; mul = 1; add = 0; bi = 0; bo = 0; }

    const int c0 = blockIdx.x * 32, r0 = blockIdx.y * 64;
    if (c0 >= C || r0 >= R) return;

    __shared__ float tile[32][65];
#pragma unroll
    for (int j = 0; j < 64; j += 8)
        tile[tx][ty + j] = src[bi + (size_t)(r0 + ty + j) * C + c0 + tx];
    __syncthreads();
#pragma unroll
    for (int jc = 0; jc < 4; jc++) {
        int c = ty + jc * 8;
        __half2 v = __floats2half2_rn(tile[c][2 * tx], tile[c][2 * tx + 1]);
        *(__half2*)(dst + bo + (size_t)((c0 + c) * mul + add) * R + r0 + 2 * tx) = v;
    }
}

// ---------------------------------------------------------------------------
// Gating (exact fp32). Also emits the fp16 copy of x (g_xt).
// ---------------------------------------------------------------------------
__global__ void gating_kernel(const float* __restrict__ x) {
    int n = blockIdx.x, t = threadIdx.x;
    int warp = t >> 5, lane = t & 31;
    __shared__ float sx[D_DIM];
    __shared__ float red[8];
    __shared__ float slog[E_NUM];
    const float* xr = x + (size_t)n * D_DIM;
    float ss = 0.f;
    for (int i = t; i < D_DIM; i += 256) { float v = xr[i]; sx[i] = v; ss += v * v; }
    for (int o = 16; o; o >>= 1) ss += __shfl_down_sync(0xFFFFFFFFu, ss, o);
    if (lane == 0) red[warp] = ss;
    __syncthreads();
    for (int i = t; i < D_DIM; i += 256) g_xt[(size_t)n * D_DIM + i] = __float2half_rn(sx[i]);
    for (int j = 0; j < 2; j++) {
        int e = warp * 2 + j;
        const float* g = g_gwn + e * D_DIM;
        float d = 0.f;
        for (int i = lane; i < D_DIM; i += 32) d += sx[i] * g[i];
        for (int o = 16; o; o >>= 1) d += __shfl_down_sync(0xFFFFFFFFu, d, o);
        if (lane == 0) slog[e] = d;
    }
    __syncthreads();
    if (t == 0) {
        float ssq = 0.f;
        for (int i = 0; i < 8; i++) ssq += red[i];
        float inv = 1.0f / fmaxf(sqrtf(ssq), 1e-12f);
        float sc[E_NUM];
        for (int e = 0; e < E_NUM; e++) sc[e] = slog[e] * inv;
        int sel[KSEL]; float sw[KSEL]; float wsum = 0.f;
        for (int k = 0; k < KSEL; k++) {
            int bi = 0; float bv = -1e30f;
            for (int e = 0; e < E_NUM; e++)
                if (sc[e] > bv) { bv = sc[e]; bi = e; }
            sel[k] = bi;
            float s = 1.0f / (1.0f + __expf(-bv));
            sw[k] = s; wsum += s; sc[bi] = -1e30f;
        }
        float invw = 1.0f / wsum;
        for (int k = 0; k < KSEL; k++) {
            g_idx[n * KSEL + k] = sel[k];
            g_w[n * KSEL + k]   = sw[k] * invw;
            atomicAdd(&g_cnt[sel[k]], 1);
        }
    }
}

// scatter with in-block prefix over g_cnt
__global__ void scatter_kernel() {
    __shared__ int soff[E_NUM];
    int t = threadIdx.x;
    if (t == 0) {
        int a = 0;
        for (int e = 0; e < E_NUM; e++) { soff[e] = a; a += g_cnt[e]; }
    }
    __syncthreads();
    int id = blockIdx.x * 256 + t;
    if (id < NK) {
        int e = g_idx[id];
        int p = soff[e] + atomicAdd(&g_pos[e], 1);
        g_tok[p] = id / KSEL;
        g_tw[p]  = g_w[id];
        g_pmap[id] = p;
    }
}

// ---------------------------------------------------------------------------
// fp16 mma.sync GEMM: BM=256, BN=128, BK=64, 8 warps in 4(m)x2(n),
// warp tile 64x64 (A-dup 2, B-dup 4 -> 0.67x smem bytes/MAC vs 128x128).
// 2-stage cp.async, 1 CTA/SM (reg-bound: 128 accums/thread).
// z<16 routed expert z, z==16 shared.
// ---------------------------------------------------------------------------
#define ROWB    144
#define A_ST    (256 * ROWB)     // 36864 B
#define B_ST    (128 * ROWB)     // 18432 B
#define SMEM_BYTES (2 * A_ST + 2 * B_ST + 2048)

template <bool GU>
__global__ void __launch_bounds__(256)
mma_gemm(const __half* __restrict__ Art, const __half* __restrict__ Ash,
         const __half* __restrict__ Brt, const __half* __restrict__ Bsh,
         __half* __restrict__ outRt, void* __restrict__ outShv) {
    constexpr int KD = GU ? D_DIM : H_DIM;
    const int e = blockIdx.z;
    const bool gather = (e < E_NUM);
    const int cnt = gather ? g_cnt[e] : NTOK;
    const int m0  = blockIdx.x * 256;
    if (m0 >= cnt) return;
    int offr = 0;
    if (gather) {
        for (int q = 0; q < E_NUM; q++) offr += (q < e) ? g_cnt[q] : 0;
    }
    const int n0 = blockIdx.y * 128;

    const __half* A = gather ? Art : Ash;
    const __half* B = gather ? (Brt + (size_t)e * 1024 * KD) : Bsh;

    extern __shared__ char smc[];
    const uint32_t uA = smem_u32(smc);
    const uint32_t uB = uA + 2 * A_ST;
    int*   rtok = (int*)(smc + 2 * A_ST + 2 * B_ST);
    float* twsh = (float*)(smc + 2 * A_ST + 2 * B_ST + 1024);

    const int t = threadIdx.x;
    const int warp = t >> 5, lane = t & 31;
    const int wm = warp >> 1, wn = warp & 1;     // 4 x 2

    {   // 256 A-row indices + combine weights
        int gm = m0 + t;
        int cg = (gm < cnt) ? gm : 0;
        int src;
        if (GU) src = gather ? g_tok[offr + cg] : gm;
        else    src = gather ? (offr + gm) : gm;
        rtok[t] = src;
        twsh[t] = (GU && gather) ? g_tw[offr + cg] : 1.0f;
    }
    __syncthreads();

    // per-thread load map: A 8 chunks, B 4 chunks (16B each) per stage
    const __half* aP[8];
    const __half* bP[4];
    uint32_t aO[8], bO[4];
#pragma unroll
    for (int j = 0; j < 8; j++) {
        int cidx = t + j * 256;
        int row = cidx >> 3, kc = cidx & 7;
        aP[j] = A + (size_t)rtok[row] * KD + kc * 8;
        aO[j] = (uint32_t)(row * ROWB + kc * 16);
    }
#pragma unroll
    for (int j = 0; j < 4; j++) {
        int cidx = t + j * 256;
        int row = cidx >> 3, kc = cidx & 7;
        bP[j] = B + (size_t)(n0 + row) * KD + kc * 8;
        bO[j] = (uint32_t)(row * ROWB + kc * 16);
    }

    // ks-invariant ldsm address parts
    const uint32_t aRow = wm * 64 + (lane & 7) + ((lane >> 3) & 1) * 8;
    const uint32_t aCol = (lane >> 4) * 16;
    const uint32_t bRow0 = wn * 64 + ((lane >> 4) & 1) * 8 + (lane & 7);
    const uint32_t bCol = ((lane >> 3) & 1) * 16;

#define LOADSTAGE(s, k0) do {                                       \
        _Pragma("unroll")                                           \
        for (int j = 0; j < 8; j++)                                 \
            cp16(uA + (s) * A_ST + aO[j], aP[j] + (k0));            \
        _Pragma("unroll")                                           \
        for (int j = 0; j < 4; j++)                                 \
            cp16(uB + (s) * B_ST + bO[j], bP[j] + (k0));            \
        CP_COMMIT();                                                \
    } while (0)

    float c[4][8][4] = {};

    const int NIT = KD / 64;
    LOADSTAGE(0, 0);

    for (int i = 0; i < NIT; i++) {
        if (i + 1 < NIT) { LOADSTAGE((i + 1) & 1, (i + 1) * 64); CP_WAIT1(); }
        else             { CP_WAIT0(); }
        __syncthreads();

        const uint32_t uAs = uA + (i & 1) * A_ST;
        const uint32_t uBs = uB + (i & 1) * B_ST;
#pragma unroll
        for (int ks = 0; ks < 4; ks++) {
            uint32_t a[4][4], b[4][4];
#pragma unroll
            for (int mt = 0; mt < 4; mt++) {
                uint32_t ad = uAs + (aRow + mt * 16) * ROWB + ks * 32 + aCol;
                ldm4(a[mt][0], a[mt][1], a[mt][2], a[mt][3], ad);
            }
#pragma unroll
            for (int p = 0; p < 4; p++) {
                uint32_t ad = uBs + (bRow0 + p * 16) * ROWB + ks * 32 + bCol;
                ldm4(b[p][0], b[p][1], b[p][2], b[p][3], ad);
            }
#pragma unroll
            for (int mt = 0; mt < 4; mt++) {
#pragma unroll
                for (int nt = 0; nt < 8; nt++)
                    mma16(c[mt][nt], a[mt], b[nt >> 1][2 * (nt & 1)], b[nt >> 1][2 * (nt & 1) + 1]);
            }
        }
        __syncthreads();
    }
#undef LOADSTAGE

#pragma unroll
    for (int mt = 0; mt < 4; mt++) {
        int r0 = wm * 64 + mt * 16 + (lane >> 2);
#pragma unroll
        for (int pass = 0; pass < 2; pass++) {
            int r = r0 + pass * 8;
            int gm = m0 + r;
            if (gm < cnt) {
                if (GU) {
                    float tw = twsh[r];
                    __half* orow = (gather ? outRt + (size_t)(offr + gm) * H_DIM
                                           : (__half*)outShv + (size_t)gm * H_DIM);
#pragma unroll
                    for (int nt = 0; nt < 8; nt++) {
                        float g = c[mt][nt][pass * 2];
                        float u = c[mt][nt][pass * 2 + 1];
                        int h = (n0 + wn * 64 + nt * 8) / 2 + (lane & 3);
                        orow[h] = __float2half_rn(tw * u * g / (1.0f + __expf(-g)));
                    }
                } else if (gather) {
                    __half* orow = outRt + (size_t)(offr + gm) * D_DIM;
#pragma unroll
                    for (int nt = 0; nt < 8; nt++) {
                        int n = n0 + wn * 64 + nt * 8 + 2 * (lane & 3);
                        *(__half2*)(orow + n) =
                            __floats2half2_rn(c[mt][nt][pass * 2], c[mt][nt][pass * 2 + 1]);
                    }
                } else {
                    float* orow = (float*)outShv + (size_t)gm * D_DIM;
#pragma unroll
                    for (int nt = 0; nt < 8; nt++) {
                        int n = n0 + wn * 64 + nt * 8 + 2 * (lane & 3);
                        *(float2*)(orow + n) =
                            make_float2(c[mt][nt][pass * 2], c[mt][nt][pass * 2 + 1]);
                    }
                }
            }
        }
    }
}

// ---------------------------------------------------------------------------
// combine: out[n] (shared result) += sum_k g_yh[pmap[n,k]]  (fp16 reads)
// ---------------------------------------------------------------------------
__global__ void combine_kernel(float* __restrict__ out) {
    const int n = blockIdx.x, t = threadIdx.x;
    __shared__ int pm[KSEL];
    if (t < KSEL) pm[t] = g_pmap[n * KSEL + t];
    __syncthreads();
    float4 acc = *(const float4*)(out + (size_t)n * D_DIM + t * 4);
#pragma unroll
    for (int k = 0; k < KSEL; k++) {
        const __half2* p = (const __half2*)(g_yh + (size_t)pm[k] * D_DIM + t * 4);
        float2 v0 = __half22float2(p[0]);
        float2 v1 = __half22float2(p[1]);
        acc.x += v0.x; acc.y += v0.y; acc.z += v1.x; acc.w += v1.y;
    }
    *(float4*)(out + (size_t)n * D_DIM + t * 4) = acc;
}

// ---------------------------------------------------------------------------
// Launch:  prep2(1) gating(2) scatter(3) GU(4) DN(5) combine(6)
// ---------------------------------------------------------------------------
extern "C" void kernel_launch(void* const* d_in, const int* in_sizes, int n_in,
                              void* d_out, int out_size) {
    (void)in_sizes; (void)n_in; (void)out_size;
    const float* x       = (const float*)d_in[0];
    const float* gate_w  = (const float*)d_in[1];
    const float* w_gate  = (const float*)d_in[2];
    const float* w_up    = (const float*)d_in[3];
    const float* w_down  = (const float*)d_in[4];
    const float* sw_gate = (const float*)d_in[5];
    const float* sw_up   = (const float*)d_in[6];
    const float* sw_down = (const float*)d_in[7];
    float* out = (float*)d_out;

    cudaFuncSetAttribute(mma_gemm<true>,  cudaFuncAttributeMaxDynamicSharedMemorySize, SMEM_BYTES);
    cudaFuncSetAttribute(mma_gemm<false>, cudaFuncAttributeMaxDynamicSharedMemorySize, SMEM_BYTES);

    __half* xt; __half* wguT; __half* wdT; __half* swguT; __half* swdT;
    __half* hbuf; __half* hsbuf; __half* ybuf;
    cudaGetSymbolAddress((void**)&xt,    g_xt);
    cudaGetSymbolAddress((void**)&wguT,  g_wguT);
    cudaGetSymbolAddress((void**)&wdT,   g_wdT);
    cudaGetSymbolAddress((void**)&swguT, g_swguT);
    cudaGetSymbolAddress((void**)&swdT,  g_swdT);
    cudaGetSymbolAddress((void**)&hbuf,  g_h);
    cudaGetSymbolAddress((void**)&hsbuf, g_hs);
    cudaGetSymbolAddress((void**)&ybuf,  g_yh);

    prep2_kernel<<<dim3(32, 16, 52), dim3(32, 8)>>>(
        gate_w, w_gate, w_up, w_down, sw_gate, sw_up, sw_down, wguT, wdT, swguT, swdT);
    gating_kernel<<<NTOK, 256>>>(x);
    scatter_kernel<<<(NK + 255) / 256, 256>>>();

    // GU: routed (z<16) + shared (z==16); M-tiles of 256
    mma_gemm<true><<<dim3(NTOK / 256, 8, E_NUM + 1), 256, SMEM_BYTES>>>(
        xt, xt, wguT, swguT, hbuf, (void*)hsbuf);

    // DN: routed -> g_yh (fp16), shared -> out (fp32)
    mma_gemm<false><<<dim3(NTOK / 256, 8, E_NUM + 1), 256, SMEM_BYTES>>>(
        hbuf, hsbuf, wdT, swdT, ybuf, (void*)out);

    combine_kernel<<<NTOK, 256>>>(out);
}

// round 12
// speedup vs baseline: 1.1405x; 1.1405x over previous
#include <cuda_runtime.h>
#include <cuda_fp16.h>
#include <cstdint>
#include <math.h>

#define D_DIM 1024
#define H_DIM 512
#define E_NUM 16
#define NTOK  4096
#define KSEL  8
#define NK    (NTOK * KSEL)

// ---------------------------------------------------------------------------
// Device scratch
// ---------------------------------------------------------------------------
__device__ float g_gwn[E_NUM * D_DIM];
__device__ int   g_idx[NK];
__device__ float g_w[NK];
__device__ int   g_cnt[E_NUM];
__device__ int   g_pos[E_NUM];
__device__ int   g_tok[NK + 128];
__device__ float g_tw[NK + 128];
__device__ int   g_pmap[NK];

__device__ __half g_xt[(size_t)NTOK * D_DIM];                // fp16 x
__device__ __half g_wguT[(size_t)E_NUM * 2 * H_DIM * D_DIM]; // [E][2H][D] interleaved gate/up
__device__ __half g_wdT [(size_t)E_NUM * D_DIM * H_DIM];     // [E][D][H]
__device__ __half g_swguT[(size_t)2 * H_DIM * D_DIM];
__device__ __half g_swdT [(size_t)D_DIM * H_DIM];

__device__ __half g_h [((size_t)NK + 128) * H_DIM];          // routed hidden (weighted)
__device__ __half g_hs[(size_t)NTOK * H_DIM];                // shared hidden
__device__ __half g_yh[(size_t)NK * D_DIM];                  // routed down output (fp16)

// ---------------------------------------------------------------------------
// Helpers (sm_80-compatible PTX only — harness compiles for plain sm_100)
// ---------------------------------------------------------------------------
__device__ __forceinline__ uint32_t smem_u32(const void* p) {
    uint32_t a;
    asm("{ .reg .u64 t; cvta.to.shared.u64 t, %1; cvt.u32.u64 %0, t; }" : "=r"(a) : "l"(p));
    return a;
}
__device__ __forceinline__ void cp16(uint32_t dst, const void* src) {
    asm volatile("cp.async.cg.shared.global [%0], [%1], 16;" :: "r"(dst), "l"(src));
}
#define CP_COMMIT() asm volatile("cp.async.commit_group;" ::: "memory")
#define CP_WAIT1()  asm volatile("cp.async.wait_group 1;" ::: "memory")

__device__ __forceinline__ void ldm4(uint32_t& r0, uint32_t& r1, uint32_t& r2, uint32_t& r3,
                                     uint32_t a) {
    asm volatile("ldmatrix.sync.aligned.m8n8.x4.shared.b16 {%0,%1,%2,%3}, [%4];"
                 : "=r"(r0), "=r"(r1), "=r"(r2), "=r"(r3) : "r"(a));
}
__device__ __forceinline__ void mma16(float* c, const uint32_t* a, uint32_t b0, uint32_t b1) {
    asm volatile("mma.sync.aligned.m16n8k16.row.col.f32.f16.f16.f32 "
                 "{%0,%1,%2,%3}, {%4,%5,%6,%7}, {%8,%9}, {%0,%1,%2,%3};"
                 : "+f"(c[0]), "+f"(c[1]), "+f"(c[2]), "+f"(c[3])
                 : "r"(a[0]), "r"(a[1]), "r"(a[2]), "r"(a[3]), "r"(b0), "r"(b1));
}

// ---------------------------------------------------------------------------
// gwnorm: small, must precede gating (gating reads g_gwn). Also zeroes counters.
// ---------------------------------------------------------------------------
__global__ void gwnorm_kernel(const float* __restrict__ gw) {
    int e = blockIdx.x, t = threadIdx.x;
    if (e == 0 && t < E_NUM) { g_cnt[t] = 0; g_pos[t] = 0; }
    __shared__ float red[8];
    float ss = 0.f;
    for (int i = t; i < D_DIM; i += 256) { float v = gw[e * D_DIM + i]; ss += v * v; }
    for (int o = 16; o; o >>= 1) ss += __shfl_down_sync(0xFFFFFFFFu, ss, o);
    if ((t & 31) == 0) red[t >> 5] = ss;
    __syncthreads();
    __shared__ float s_inv;
    if (t == 0) {
        float tot = 0.f;
        for (int i = 0; i < 8; i++) tot += red[i];
        s_inv = 1.0f / fmaxf(sqrtf(tot), 1e-12f);
    }
    __syncthreads();
    float inv = s_inv;
    for (int i = t; i < D_DIM; i += 256) g_gwn[e * D_DIM + i] = gw[e * D_DIM + i] * inv;
}

// ---------------------------------------------------------------------------
// fused gating + weight-prep: flat 1D grid.
//   bid < NTOK            : gating for token bid (exact fp32; also emits g_xt fp16)
//   bid >= NTOK           : transpose-convert job p = bid - NTOK
//                           z = p >> 9 (0..50), x-tile = p & 31, y-tile = (p >> 5) & 15
// ---------------------------------------------------------------------------
__global__ void fused_pg_kernel(const float* __restrict__ x,
                                const float* __restrict__ wg, const float* __restrict__ wu,
                                const float* __restrict__ wd, const float* __restrict__ swg,
                                const float* __restrict__ swu, const float* __restrict__ swd,
                                __half* __restrict__ wguT, __half* __restrict__ wdT,
                                __half* __restrict__ swguT, __half* __restrict__ swdT) {
    const int bid = blockIdx.x;
    const int t = threadIdx.x;

    if (bid < NTOK) {
        // ---- gating ----
        const int n = bid;
        const int warp = t >> 5, lane = t & 31;
        __shared__ float sx[D_DIM];
        __shared__ float red[8];
        __shared__ float slog[E_NUM];
        const float* xr = x + (size_t)n * D_DIM;
        float ss = 0.f;
        for (int i = t; i < D_DIM; i += 256) { float v = xr[i]; sx[i] = v; ss += v * v; }
        for (int o = 16; o; o >>= 1) ss += __shfl_down_sync(0xFFFFFFFFu, ss, o);
        if (lane == 0) red[warp] = ss;
        __syncthreads();
        for (int i = t; i < D_DIM; i += 256) g_xt[(size_t)n * D_DIM + i] = __float2half_rn(sx[i]);
        for (int j = 0; j < 2; j++) {
            int e = warp * 2 + j;
            const float* g = g_gwn + e * D_DIM;
            float d = 0.f;
            for (int i = lane; i < D_DIM; i += 32) d += sx[i] * g[i];
            for (int o = 16; o; o >>= 1) d += __shfl_down_sync(0xFFFFFFFFu, d, o);
            if (lane == 0) slog[e] = d;
        }
        __syncthreads();
        if (t == 0) {
            float ssq = 0.f;
            for (int i = 0; i < 8; i++) ssq += red[i];
            float inv = 1.0f / fmaxf(sqrtf(ssq), 1e-12f);
            float sc[E_NUM];
            for (int e = 0; e < E_NUM; e++) sc[e] = slog[e] * inv;
            int sel[KSEL]; float sw[KSEL]; float wsum = 0.f;
            for (int k = 0; k < KSEL; k++) {
                int bi = 0; float bv = -1e30f;
                for (int e = 0; e < E_NUM; e++)
                    if (sc[e] > bv) { bv = sc[e]; bi = e; }
                sel[k] = bi;
                float s = 1.0f / (1.0f + __expf(-bv));
                sw[k] = s; wsum += s; sc[bi] = -1e30f;
            }
            float invw = 1.0f / wsum;
            for (int k = 0; k < KSEL; k++) {
                g_idx[n * KSEL + k] = sel[k];
                g_w[n * KSEL + k]   = sw[k] * invw;
                atomicAdd(&g_cnt[sel[k]], 1);
            }
        }
        return;
    }

    // ---- transpose-convert job ----
    const int p = bid - NTOK;
    const int z = p >> 9;
    const int xt_ = p & 31;          // c-tile
    const int yt_ = (p >> 5) & 15;   // r-tile
    const int tx = t & 31, ty = t >> 5;

    const float* src; __half* dst;
    int R, C, mul, add;
    size_t bi, bo;
    if (z < 16)       { int e = z;      src = wg;  dst = wguT;  R = D_DIM; C = H_DIM; mul = 2; add = 0; bi = (size_t)e * R * C; bo = bi * 2; }
    else if (z < 32)  { int e = z - 16; src = wu;  dst = wguT;  R = D_DIM; C = H_DIM; mul = 2; add = 1; bi = (size_t)e * R * C; bo = bi * 2; }
    else if (z < 48)  { int e = z - 32; src = wd;  dst = wdT;   R = H_DIM; C = D_DIM; mul = 1; add = 0; bi = (size_t)e * R * C; bo = bi; }
    else if (z == 48) { src = swg; dst = swguT; R = D_DIM; C = H_DIM; mul = 2; add = 0; bi = 0; bo = 0; }
    else if (z == 49) { src = swu; dst = swguT; R = D_DIM; C = H_DIM; mul = 2; add = 1; bi = 0; bo = 0; }
    else              { src = swd; dst = swdT;  R = H_DIM; C = D_DIM; mul = 1; add = 0; bi = 0; bo = 0; }

    const int c0 = xt_ * 32, r0 = yt_ * 64;
    if (c0 >= C || r0 >= R) return;

    __shared__ float tile[32][65];
#pragma unroll
    for (int j = 0; j < 64; j += 8)
        tile[tx][ty + j] = src[bi + (size_t)(r0 + ty + j) * C + c0 + tx];
    __syncthreads();
#pragma unroll
    for (int jc = 0; jc < 4; jc++) {
        int c = ty + jc * 8;
        __half2 v = __floats2half2_rn(tile[c][2 * tx], tile[c][2 * tx + 1]);
        *(__half2*)(dst + bo + (size_t)((c0 + c) * mul + add) * R + r0 + 2 * tx) = v;
    }
}

// scatter with in-block prefix over g_cnt
__global__ void scatter_kernel() {
    __shared__ int soff[E_NUM];
    int t = threadIdx.x;
    if (t == 0) {
        int a = 0;
        for (int e = 0; e < E_NUM; e++) { soff[e] = a; a += g_cnt[e]; }
    }
    __syncthreads();
    int id = blockIdx.x * 256 + t;
    if (id < NK) {
        int e = g_idx[id];
        int p = soff[e] + atomicAdd(&g_pos[e], 1);
        g_tok[p] = id / KSEL;
        g_tw[p]  = g_w[id];
        g_pmap[id] = p;
    }
}

// ---------------------------------------------------------------------------
// fp16 mma.sync GEMM (R9/R10 proven geometry): block 128x128, BK=64,
// warp grid 2(m)x4(n), m16n8k16, 3-stage cp.async, 2 CTAs/SM.
// NEW: warp-staggered ks order ((j+warp)&3) to de-phase LDSM vs HMMA bursts
// across warps so the LSU and tensor pipes run concurrently.
// z<16 routed expert z, z==16 shared.
// ---------------------------------------------------------------------------
#define ROWB    144
#define TILE_HB (128 * ROWB)
#define NSTG    3
#define SMEM_BYTES (2 * NSTG * TILE_HB + 1024)

template <bool GU>
__global__ void __launch_bounds__(256)
mma_gemm(const __half* __restrict__ Art, const __half* __restrict__ Ash,
         const __half* __restrict__ Brt, const __half* __restrict__ Bsh,
         __half* __restrict__ outRt, void* __restrict__ outShv) {
    constexpr int KD = GU ? D_DIM : H_DIM;
    const int e = blockIdx.z;
    const bool gather = (e < E_NUM);
    const int cnt = gather ? g_cnt[e] : NTOK;
    const int m0  = blockIdx.x * 128;
    if (m0 >= cnt) return;
    int offr = 0;
    if (gather) {
        for (int q = 0; q < E_NUM; q++) offr += (q < e) ? g_cnt[q] : 0;
    }
    const int n0 = blockIdx.y * 128;

    const __half* A = gather ? Art : Ash;
    const __half* B = gather ? (Brt + (size_t)e * 1024 * KD) : Bsh;

    extern __shared__ char smc[];
    const uint32_t uA = smem_u32(smc);
    const uint32_t uB = uA + NSTG * TILE_HB;
    int*   rtok = (int*)(smc + 2 * NSTG * TILE_HB);
    float* twsh = (float*)(smc + 2 * NSTG * TILE_HB + 512);

    const int t = threadIdx.x;
    const int warp = t >> 5, lane = t & 31;
    const int wm = warp >> 2, wn = warp & 3;

    if (t < 128) {
        int gm = m0 + t;
        int cg = (gm < cnt) ? gm : 0;
        int src;
        if (GU) src = gather ? g_tok[offr + cg] : gm;
        else    src = gather ? (offr + gm) : gm;
        rtok[t] = src;
        twsh[t] = (GU && gather) ? g_tw[offr + cg] : 1.0f;
    }
    __syncthreads();

    const __half* aP[4];
    const __half* bP[4];
    uint32_t sOff[4];
#pragma unroll
    for (int j = 0; j < 4; j++) {
        int cidx = t + j * 256;
        int row = cidx >> 3, kc = cidx & 7;
        aP[j] = A + (size_t)rtok[row] * KD + kc * 8;
        bP[j] = B + (size_t)(n0 + row) * KD + kc * 8;
        sOff[j] = (uint32_t)(row * ROWB + kc * 16);
    }

    // ks-invariant ldsm address parts
    const uint32_t aRow = wm * 64 + (lane & 7) + ((lane >> 3) & 1) * 8;
    const uint32_t aCol = (lane >> 4) * 16;
    const uint32_t bRow0 = wn * 32 + ((lane >> 4) & 1) * 8 + (lane & 7);
    const uint32_t bCol = ((lane >> 3) & 1) * 16;

#define LOADSTAGE(s, k0) do {                                       \
        _Pragma("unroll")                                           \
        for (int j = 0; j < 4; j++) {                               \
            cp16(uA + (s) * TILE_HB + sOff[j], aP[j] + (k0));       \
            cp16(uB + (s) * TILE_HB + sOff[j], bP[j] + (k0));       \
        }                                                           \
    } while (0)

    float c[4][4][4] = {};

    const int NIT = KD / 64;
    LOADSTAGE(0, 0);  CP_COMMIT();
    LOADSTAGE(1, 64); CP_COMMIT();

    for (int i = 0; i < NIT; i++) {
        CP_WAIT1();
        __syncthreads();
        const int ld = i + 2;
        if (ld < NIT) LOADSTAGE(ld % NSTG, ld * 64);
        CP_COMMIT();

        const int s = i % NSTG;
        const uint32_t uAs = uA + s * TILE_HB;
        const uint32_t uBs = uB + s * TILE_HB;
#pragma unroll
        for (int j = 0; j < 4; j++) {
            const int ks = (j + warp) & 3;   // warp-staggered phase
            uint32_t a[4][4], b[2][4];
#pragma unroll
            for (int mt = 0; mt < 4; mt++) {
                uint32_t ad = uAs + (aRow + mt * 16) * ROWB + ks * 32 + aCol;
                ldm4(a[mt][0], a[mt][1], a[mt][2], a[mt][3], ad);
            }
#pragma unroll
            for (int p = 0; p < 2; p++) {
                uint32_t ad = uBs + (bRow0 + p * 16) * ROWB + ks * 32 + bCol;
                ldm4(b[p][0], b[p][1], b[p][2], b[p][3], ad);
            }
#pragma unroll
            for (int mt = 0; mt < 4; mt++) {
#pragma unroll
                for (int nt = 0; nt < 4; nt++)
                    mma16(c[mt][nt], a[mt], b[nt >> 1][2 * (nt & 1)], b[nt >> 1][2 * (nt & 1) + 1]);
            }
        }
    }
#undef LOADSTAGE

#pragma unroll
    for (int mt = 0; mt < 4; mt++) {
        int r0 = wm * 64 + mt * 16 + (lane >> 2);
#pragma unroll
        for (int pass = 0; pass < 2; pass++) {
            int r = r0 + pass * 8;
            int gm = m0 + r;
            if (gm < cnt) {
                if (GU) {
                    float tw = twsh[r];
                    __half* orow = (gather ? outRt + (size_t)(offr + gm) * H_DIM
                                           : (__half*)outShv + (size_t)gm * H_DIM);
#pragma unroll
                    for (int nt = 0; nt < 4; nt++) {
                        float g = c[mt][nt][pass * 2];
                        float u = c[mt][nt][pass * 2 + 1];
                        int h = (n0 + wn * 32 + nt * 8) / 2 + (lane & 3);
                        orow[h] = __float2half_rn(tw * u * g / (1.0f + __expf(-g)));
                    }
                } else if (gather) {
                    __half* orow = outRt + (size_t)(offr + gm) * D_DIM;
#pragma unroll
                    for (int nt = 0; nt < 4; nt++) {
                        int n = n0 + wn * 32 + nt * 8 + 2 * (lane & 3);
                        *(__half2*)(orow + n) =
                            __floats2half2_rn(c[mt][nt][pass * 2], c[mt][nt][pass * 2 + 1]);
                    }
                } else {
                    float* orow = (float*)outShv + (size_t)gm * D_DIM;
#pragma unroll
                    for (int nt = 0; nt < 4; nt++) {
                        int n = n0 + wn * 32 + nt * 8 + 2 * (lane & 3);
                        *(float2*)(orow + n) =
                            make_float2(c[mt][nt][pass * 2], c[mt][nt][pass * 2 + 1]);
                    }
                }
            }
        }
    }
}

// ---------------------------------------------------------------------------
// combine: out[n] (shared result) += sum_k g_yh[pmap[n,k]]  (fp16 reads)
// ---------------------------------------------------------------------------
__global__ void combine_kernel(float* __restrict__ out) {
    const int n = blockIdx.x, t = threadIdx.x;
    __shared__ int pm[KSEL];
    if (t < KSEL) pm[t] = g_pmap[n * KSEL + t];
    __syncthreads();
    float4 acc = *(const float4*)(out + (size_t)n * D_DIM + t * 4);
#pragma unroll
    for (int k = 0; k < KSEL; k++) {
        const __half2* p = (const __half2*)(g_yh + (size_t)pm[k] * D_DIM + t * 4);
        float2 v0 = __half22float2(p[0]);
        float2 v1 = __half22float2(p[1]);
        acc.x += v0.x; acc.y += v0.y; acc.z += v1.x; acc.w += v1.y;
    }
    *(float4*)(out + (size_t)n * D_DIM + t * 4) = acc;
}

// ---------------------------------------------------------------------------
// Launch:  gwnorm(1) fused_pg(2) scatter(3) GU(4) DN(5) combine(6)
// ---------------------------------------------------------------------------
extern "C" void kernel_launch(void* const* d_in, const int* in_sizes, int n_in,
                              void* d_out, int out_size) {
    (void)in_sizes; (void)n_in; (void)out_size;
    const float* x       = (const float*)d_in[0];
    const float* gate_w  = (const float*)d_in[1];
    const float* w_gate  = (const float*)d_in[2];
    const float* w_up    = (const float*)d_in[3];
    const float* w_down  = (const float*)d_in[4];
    const float* sw_gate = (const float*)d_in[5];
    const float* sw_up   = (const float*)d_in[6];
    const float* sw_down = (const float*)d_in[7];
    float* out = (float*)d_out;

    cudaFuncSetAttribute(mma_gemm<true>,  cudaFuncAttributeMaxDynamicSharedMemorySize, SMEM_BYTES);
    cudaFuncSetAttribute(mma_gemm<false>, cudaFuncAttributeMaxDynamicSharedMemorySize, SMEM_BYTES);

    __half* xt; __half* wguT; __half* wdT; __half* swguT; __half* swdT;
    __half* hbuf; __half* hsbuf; __half* ybuf;
    cudaGetSymbolAddress((void**)&xt,    g_xt);
    cudaGetSymbolAddress((void**)&wguT,  g_wguT);
    cudaGetSymbolAddress((void**)&wdT,   g_wdT);
    cudaGetSymbolAddress((void**)&swguT, g_swguT);
    cudaGetSymbolAddress((void**)&swdT,  g_swdT);
    cudaGetSymbolAddress((void**)&hbuf,  g_h);
    cudaGetSymbolAddress((void**)&hsbuf, g_hs);
    cudaGetSymbolAddress((void**)&ybuf,  g_yh);

    gwnorm_kernel<<<E_NUM, 256>>>(gate_w);

    // gating (4096 blocks) + 51 transpose jobs (26112 blocks) fused
    fused_pg_kernel<<<NTOK + 51 * 512, 256>>>(
        x, w_gate, w_up, w_down, sw_gate, sw_up, sw_down, wguT, wdT, swguT, swdT);

    scatter_kernel<<<(NK + 255) / 256, 256>>>();

    // GU: routed (z<16) + shared (z==16)   -- capture slot 4
    mma_gemm<true><<<dim3(32, 8, E_NUM + 1), 256, SMEM_BYTES>>>(
        xt, xt, wguT, swguT, hbuf, (void*)hsbuf);

    // DN: routed -> g_yh (fp16), shared -> out (fp32)
    mma_gemm<false><<<dim3(32, 8, E_NUM + 1), 256, SMEM_BYTES>>>(
        hbuf, hsbuf, wdT, swdT, ybuf, (void*)out);

    combine_kernel<<<NTOK, 256>>>(out);
}